// round 14
// baseline (speedup 1.0000x reference)
#include <cuda_runtime.h>
#include <cuda_bf16.h>

// Problem constants
#define BSZ   2
#define SEQ   2048
#define HIDN  1024
#define HEADS 16
#define HD    64
#define NQB   32            // SEQ / 64
#define MROWS (BSZ*SEQ)     // 4096

typedef __nv_bfloat16 bf16;

// Scratch (device globals)
__device__ bf16 g_xh[MROWS*HIDN], g_xl[MROWS*HIDN];
__device__ bf16 g_w8[8][HIDN*HIDN];       // Wq h,l  Wk h,l  Wv h,l  Wo h,l
__device__ bf16 g_qh[BSZ*HEADS*SEQ*HD], g_ql[BSZ*HEADS*SEQ*HD];
__device__ bf16 g_kh[BSZ*HEADS*SEQ*HD], g_kl[BSZ*HEADS*SEQ*HD];
__device__ bf16 g_vh[BSZ*HEADS*SEQ*HD], g_vl[BSZ*HEADS*SEQ*HD];
__device__ bf16 g_ah[MROWS*HIDN], g_al[MROWS*HIDN];   // attn out [B,S,HID]
__device__ unsigned g_ctr[2];                          // tile counters

// ===========================================================================
// helpers
// ===========================================================================
__device__ __forceinline__ unsigned smem_u32(const void* p) {
    unsigned a;
    asm("{ .reg .u64 t; cvta.to.shared.u64 t, %1; cvt.u32.u64 %0, t; }"
        : "=r"(a) : "l"(p));
    return a;
}
__device__ __forceinline__ void ldsm4(unsigned* r, unsigned addr) {
    asm volatile("ldmatrix.sync.aligned.m8n8.x4.shared.b16 {%0,%1,%2,%3}, [%4];"
                 : "=r"(r[0]), "=r"(r[1]), "=r"(r[2]), "=r"(r[3]) : "r"(addr));
}
__device__ __forceinline__ void ldsm4t(unsigned* r, unsigned addr) {
    asm volatile("ldmatrix.sync.aligned.m8n8.x4.trans.shared.b16 {%0,%1,%2,%3}, [%4];"
                 : "=r"(r[0]), "=r"(r[1]), "=r"(r[2]), "=r"(r[3]) : "r"(addr));
}
__device__ __forceinline__ void mma16816(float* c, const unsigned* a,
                                         const unsigned* b) {
    asm volatile(
        "mma.sync.aligned.m16n8k16.row.col.f32.bf16.bf16.f32 "
        "{%0,%1,%2,%3}, {%4,%5,%6,%7}, {%8,%9}, {%0,%1,%2,%3};"
        : "+f"(c[0]), "+f"(c[1]), "+f"(c[2]), "+f"(c[3])
        : "r"(a[0]), "r"(a[1]), "r"(a[2]), "r"(a[3]), "r"(b[0]), "r"(b[1]));
}
__device__ __forceinline__ unsigned pack_bf16(bf16 x, bf16 y) {
    return ((unsigned)__bfloat16_as_ushort(y) << 16) | __bfloat16_as_ushort(x);
}
#define CP_ASYNC16(dst, src) \
    asm volatile("cp.async.cg.shared.global [%0], [%1], 16;" :: "r"(dst), "l"(src))
#define CP_COMMIT() asm volatile("cp.async.commit_group;" ::: "memory")
#define CP_WAIT0()  asm volatile("cp.async.wait_group 0;" ::: "memory")
#define CP_WAIT1()  asm volatile("cp.async.wait_group 1;" ::: "memory")

// ===========================================================================
// Fused split kernel: x + 4 weights in one launch; also resets tile counters.
// ===========================================================================
#define XBLK 2048            // (MROWS*HIDN/8)/256
#define WBLK 512             // (HIDN*HIDN/8)/256

__global__ void split_all(const float* __restrict__ x,
                          const float* __restrict__ Wq,
                          const float* __restrict__ Wk,
                          const float* __restrict__ Wv,
                          const float* __restrict__ Wo,
                          bf16* __restrict__ xh, bf16* __restrict__ xl,
                          bf16* __restrict__ w8)
{
    if (blockIdx.x == 0 && threadIdx.x == 0) { g_ctr[0] = 0; g_ctr[1] = 0; }

    const float* src;
    bf16 *hi, *lo;
    int lb;
    const int W2 = HIDN * HIDN;
    if (blockIdx.x < XBLK) {
        src = x; hi = xh; lo = xl; lb = blockIdx.x;
    } else {
        const int wi = (blockIdx.x - XBLK) / WBLK;        // 0..3
        lb = (blockIdx.x - XBLK) % WBLK;
        src = (wi == 0) ? Wq : (wi == 1) ? Wk : (wi == 2) ? Wv : Wo;
        hi = w8 + (size_t)(2 * wi) * W2;
        lo = w8 + (size_t)(2 * wi + 1) * W2;
    }

    const int base = (lb * 256 + threadIdx.x) * 2;
    float4 va = ((const float4*)src)[base];
    float4 vb = ((const float4*)src)[base + 1];
#pragma unroll
    for (int u = 0; u < 2; u++) {
        const float4 v = u ? vb : va;
        const int i = base + u;
        bf16 h0 = __float2bfloat16_rn(v.x);
        bf16 h1 = __float2bfloat16_rn(v.y);
        bf16 h2 = __float2bfloat16_rn(v.z);
        bf16 h3 = __float2bfloat16_rn(v.w);
        uint2 ho, lo2;
        ho.x = pack_bf16(h0, h1); ho.y = pack_bf16(h2, h3);
        lo2.x = pack_bf16(__float2bfloat16_rn(v.x - __bfloat162float(h0)),
                          __float2bfloat16_rn(v.y - __bfloat162float(h1)));
        lo2.y = pack_bf16(__float2bfloat16_rn(v.z - __bfloat162float(h2)),
                          __float2bfloat16_rn(v.w - __bfloat162float(h3)));
        ((uint2*)hi)[i] = ho;
        ((uint2*)lo)[i] = lo2;
    }
}

// ===========================================================================
// Persistent GEMM (unchanged from R13): tiles from global atomic counter.
// ===========================================================================
struct Job {
    const bf16* Wh; const bf16* Wl;
    const float* bias;
    bf16* Oh; bf16* Ol;
    float* Cf;
    float scl;
};

#define GST       40
#define GTILE_B   (128 * GST * 2)        // 10240 B per component tile
#define GSTAGE_B  (4 * GTILE_B)          // 40960 B
#define GSM_BYTES (2 * GSTAGE_B + 128)   // 82048 B
#define NCH2      (HIDN / 32)            // 32 chunks

__global__ __launch_bounds__(256, 2)
void gemm_pers(unsigned* ctr, int ntot,
               const bf16* __restrict__ Ah, const bf16* __restrict__ Al,
               Job j0, Job j1, Job j2)
{
    extern __shared__ char sm[];
    volatile int* slot = (volatile int*)(sm + 2 * GSTAGE_B);
    const int tid  = threadIdx.x;
    const int lane = tid & 31;
    const int wid  = tid >> 5;
    const int wm   = wid >> 2;           // 0..1
    const int wn   = wid & 3;            // 0..3

    const bf16* gsrc[4];

    auto setsrc = [&](int tile) {
        const int m  = tile >> 8;
        const int tt = tile & 255;
        const int bm = tt >> 3, bn = tt & 7;
        const Job& jb = (m == 0) ? j0 : (m == 1 ? j1 : j2);
        gsrc[0] = Ah + (size_t)bm * 128 * HIDN;
        gsrc[1] = Al + (size_t)bm * 128 * HIDN;
        gsrc[2] = jb.Wh + (size_t)bn * 128 * HIDN;
        gsrc[3] = jb.Wl + (size_t)bn * 128 * HIDN;
    };

    auto issue = [&](int kt, int buf) {
        char* st = sm + buf * GSTAGE_B;
#pragma unroll
        for (int t4 = 0; t4 < 4; t4++) {
#pragma unroll
            for (int j = 0; j < 2; j++) {
                const int ch = tid + j * 256;       // 0..511
                const int row = ch >> 2, cc = ch & 3;
                unsigned dst = smem_u32(st + t4 * GTILE_B + (row * GST + cc * 8) * 2);
                const bf16* src = gsrc[t4] + (size_t)row * HIDN + kt + cc * 8;
                CP_ASYNC16(dst, src);
            }
        }
        CP_COMMIT();
    };

    if (tid == 0) *slot = (int)atomicAdd(ctr, 1u);
    __syncthreads();
    int t = *slot;
    if (t >= ntot) return;
    setsrc(t);
    issue(0, 0);

    const int fr = lane & 15;
    const int fc = (lane >> 4) << 3;
    const int g = lane >> 2, tq = lane & 3;

    while (true) {
        float acc[4][4][4];
#pragma unroll
        for (int i = 0; i < 4; i++)
#pragma unroll
            for (int j = 0; j < 4; j++)
#pragma unroll
                for (int k = 0; k < 4; k++) acc[i][j][k] = 0.f;

        int tn = ntot;
        for (int c = 0; c < NCH2; c++) {
            CP_WAIT0();
            __syncthreads();
            if (c == NCH2 - 2 && tid == 0) *slot = (int)atomicAdd(ctr, 1u);
            if (c < NCH2 - 1) {
                issue((c + 1) * 32, (c + 1) & 1);
            } else {
                tn = *slot;
                if (tn < ntot) { setsrc(tn); issue(0, 0); }
            }

            const unsigned sb = smem_u32(sm) + (c & 1) * GSTAGE_B;
            const unsigned uAh = sb, uAl = sb + GTILE_B;
            const unsigned uWh = sb + 2 * GTILE_B, uWl = sb + 3 * GTILE_B;

#pragma unroll
            for (int ks = 0; ks < 2; ks++) {
                const int kcol = ks * 16 + fc;
                unsigned ah[4][4], al[4][4], bh[4][2], bl[4][2];
#pragma unroll
                for (int mt = 0; mt < 4; mt++) {
                    const unsigned off = ((wm * 64 + mt * 16 + fr) * GST + kcol) * 2;
                    ldsm4(ah[mt], uAh + off);
                    ldsm4(al[mt], uAl + off);
                }
#pragma unroll
                for (int ntp = 0; ntp < 2; ntp++) {
                    const unsigned off = ((wn * 32 + ntp * 16 + fr) * GST + kcol) * 2;
                    unsigned r[4];
                    ldsm4(r, uWh + off);
                    bh[2*ntp][0] = r[0]; bh[2*ntp+1][0] = r[1];
                    bh[2*ntp][1] = r[2]; bh[2*ntp+1][1] = r[3];
                    ldsm4(r, uWl + off);
                    bl[2*ntp][0] = r[0]; bl[2*ntp+1][0] = r[1];
                    bl[2*ntp][1] = r[2]; bl[2*ntp+1][1] = r[3];
                }
#pragma unroll
                for (int mt = 0; mt < 4; mt++)
#pragma unroll
                    for (int nt = 0; nt < 4; nt++) {
                        mma16816(acc[mt][nt], ah[mt], bh[nt]);
                        mma16816(acc[mt][nt], ah[mt], bl[nt]);
                        mma16816(acc[mt][nt], al[mt], bh[nt]);
                    }
            }
        }

        {
            const int m  = t >> 8;
            const int tt = t & 255;
            const int bm = tt >> 3, bn = tt & 7;
            const Job& jb = (m == 0) ? j0 : (m == 1 ? j1 : j2);
#pragma unroll
            for (int mt = 0; mt < 4; mt++) {
#pragma unroll
                for (int nt = 0; nt < 4; nt++) {
                    const int n = bn * 128 + wn * 32 + nt * 8 + 2 * tq;
                    const float2 bi = *(const float2*)(jb.bias + n);
                    const int m0 = bm * 128 + wm * 64 + mt * 16 + g;
#pragma unroll
                    for (int half = 0; half < 2; half++) {
                        const int mr = m0 + half * 8;
                        float vx = (acc[mt][nt][half * 2 + 0] + bi.x) * jb.scl;
                        float vy = (acc[mt][nt][half * 2 + 1] + bi.y) * jb.scl;
                        if (jb.Cf) {
                            *(float2*)(jb.Cf + (size_t)mr * HIDN + n) =
                                make_float2(vx, vy);
                        } else {
                            const int b = mr >> 11, s = mr & 2047;
                            const int hh = n >> 6, d = n & 63;
                            const size_t idx =
                                (((size_t)(b * HEADS + hh)) * SEQ + s) * HD + d;
                            bf16 h0 = __float2bfloat16_rn(vx);
                            bf16 h1 = __float2bfloat16_rn(vy);
                            *(unsigned*)(jb.Oh + idx) = pack_bf16(h0, h1);
                            *(unsigned*)(jb.Ol + idx) = pack_bf16(
                                __float2bfloat16_rn(vx - __bfloat162float(h0)),
                                __float2bfloat16_rn(vy - __bfloat162float(h1)));
                        }
                    }
                }
            }
        }

        if (tn >= ntot) return;
        t = tn;
    }
}

// ===========================================================================
// Block-causal flash attention — SMEM-slim for 3 CTAs/SM:
// K double-buffered (prefetched a full iteration ahead), V single-buffered
// (issued at iteration top; lands during S-MMA + softmax), xm/xl single.
// ===========================================================================
#define AST     72
#define ATILE_B (64 * AST * 2)        // 9216 B
#define AOFF_K  18432                 // after Qh, Ql
#define AOFF_V  (AOFF_K + 2 * 2 * ATILE_B)   // 55296
#define AOFF_XM (AOFF_V + 2 * ATILE_B)       // 73728
#define ATTN_SMEM (AOFF_XM + 1024)    // 74752 B -> 3 CTAs/SM

__global__ __launch_bounds__(256, 3)
void attn_mma2(const bf16* __restrict__ gqh, const bf16* __restrict__ gql,
               const bf16* __restrict__ gkh, const bf16* __restrict__ gkl,
               const bf16* __restrict__ gvh, const bf16* __restrict__ gvl,
               bf16* __restrict__ goh, bf16* __restrict__ gol)
{
    extern __shared__ char sm[];
    const int qb = NQB - 1 - blockIdx.x;
    const int h = blockIdx.y, b = blockIdx.z;
    const int tid  = threadIdx.x;
    const int lane = tid & 31;
    const int wid  = tid >> 5;
    const int wm   = wid >> 1;
    const int wn   = wid & 1;
    const int fr = lane & 15, fc = (lane >> 4) << 3;
    const int g  = lane >> 2, t = lane & 3;
    const int vkr = ((lane >> 4) << 3) + (lane & 7);
    const int vnc = ((lane >> 3) & 1) << 3;

    const size_t hb = ((size_t)(b * HEADS + h)) * SEQ * HD;
    const bf16* src_k[4];
    src_k[0] = gkh + hb; src_k[1] = gkl + hb;
    src_k[2] = gvh + hb; src_k[3] = gvl + hb;

    auto issueK = [&](int kb) {
        char* st = sm + AOFF_K + (kb & 1) * (2 * ATILE_B);
        const size_t koff = (size_t)kb * 64 * HD;
#pragma unroll
        for (int t4 = 0; t4 < 2; t4++) {
#pragma unroll
            for (int j = 0; j < 2; j++) {
                const int ch = tid + j * 256;
                const int row = ch >> 3, cc = ch & 7;
                unsigned dst = smem_u32(st + t4 * ATILE_B + (row * AST + cc * 8) * 2);
                CP_ASYNC16(dst, src_k[t4] + koff + row * HD + cc * 8);
            }
        }
        CP_COMMIT();
    };
    auto issueV = [&](int kb) {
        char* st = sm + AOFF_V;
        const size_t koff = (size_t)kb * 64 * HD;
#pragma unroll
        for (int t4 = 2; t4 < 4; t4++) {
#pragma unroll
            for (int j = 0; j < 2; j++) {
                const int ch = tid + j * 256;
                const int row = ch >> 3, cc = ch & 7;
                unsigned dst = smem_u32(st + (t4 - 2) * ATILE_B + (row * AST + cc * 8) * 2);
                CP_ASYNC16(dst, src_k[t4] + koff + row * HD + cc * 8);
            }
        }
        CP_COMMIT();
    };

    issueK(0);

    // Q tiles (plain loads, once)
    {
        const bf16* qh = gqh + hb + (size_t)qb * 64 * HD;
        const bf16* ql = gql + hb + (size_t)qb * 64 * HD;
#pragma unroll
        for (int j = 0; j < 2; j++) {
            const int ch = tid + j * 256;
            const int row = ch >> 3, cc = ch & 7;
            *(uint4*)(sm + (row * AST + cc * 8) * 2) =
                *(const uint4*)(qh + row * HD + cc * 8);
            *(uint4*)(sm + ATILE_B + (row * AST + cc * 8) * 2) =
                *(const uint4*)(ql + row * HD + cc * 8);
        }
    }

    const unsigned uQh = smem_u32(sm), uQl = uQh + ATILE_B;
    const unsigned uVh = smem_u32(sm) + AOFF_V, uVl = uVh + ATILE_B;
    float* xm = (float*)(sm + AOFF_XM);
    float* xl = (float*)(sm + AOFF_XM + 512);

    float o_acc[8][4];
#pragma unroll
    for (int i = 0; i < 8; i++)
#pragma unroll
        for (int j = 0; j < 4; j++) o_acc[i][j] = 0.f;
    float m0r = -1e30f, m1r = -1e30f, l0r = 0.f, l1r = 0.f;

    for (int kb = 0; kb <= qb; kb++) {
        CP_WAIT0();               // K_kb resident (issued a full iteration ago)
        __syncthreads();          // PV(kb-1) done -> V buffer free; xm/xl free
        issueV(kb);
        if (kb < qb) issueK(kb + 1);

        const unsigned uKh = smem_u32(sm) + AOFF_K + (kb & 1) * (2 * ATILE_B);
        const unsigned uKl = uKh + ATILE_B;

        float sfr[4][4];
#pragma unroll
        for (int i = 0; i < 4; i++)
#pragma unroll
            for (int j = 0; j < 4; j++) sfr[i][j] = 0.f;

#pragma unroll
        for (int ks = 0; ks < 4; ks++) {
            const int kcol = ks * 16 + fc;
            unsigned qa_h[4], qa_l[4];
            const unsigned offa = ((wm * 16 + fr) * AST + kcol) * 2;
            ldsm4(qa_h, uQh + offa);
            ldsm4(qa_l, uQl + offa);
#pragma unroll
            for (int ntp = 0; ntp < 2; ntp++) {
                const unsigned offb = ((wn * 32 + ntp * 16 + fr) * AST + kcol) * 2;
                unsigned rh[4], rl[4];
                ldsm4(rh, uKh + offb);
                ldsm4(rl, uKl + offb);
                unsigned bh0[2] = {rh[0], rh[2]}, bh1[2] = {rh[1], rh[3]};
                unsigned bl0[2] = {rl[0], rl[2]}, bl1[2] = {rl[1], rl[3]};
                mma16816(sfr[2*ntp],   qa_h, bh0);
                mma16816(sfr[2*ntp],   qa_h, bl0);
                mma16816(sfr[2*ntp],   qa_l, bh0);
                mma16816(sfr[2*ntp+1], qa_h, bh1);
                mma16816(sfr[2*ntp+1], qa_h, bl1);
                mma16816(sfr[2*ntp+1], qa_l, bh1);
            }
        }

        // register softmax (local max/sum over this warp's k-half)
        float pm0 = sfr[0][0], pm1 = sfr[0][2];
#pragma unroll
        for (int nt = 0; nt < 4; nt++) {
            pm0 = fmaxf(pm0, fmaxf(sfr[nt][0], sfr[nt][1]));
            pm1 = fmaxf(pm1, fmaxf(sfr[nt][2], sfr[nt][3]));
        }
        pm0 = fmaxf(pm0, __shfl_xor_sync(0xffffffffu, pm0, 1));
        pm0 = fmaxf(pm0, __shfl_xor_sync(0xffffffffu, pm0, 2));
        pm1 = fmaxf(pm1, __shfl_xor_sync(0xffffffffu, pm1, 1));
        pm1 = fmaxf(pm1, __shfl_xor_sync(0xffffffffu, pm1, 2));

        float ps0 = 0.f, ps1 = 0.f;
#pragma unroll
        for (int nt = 0; nt < 4; nt++) {
            sfr[nt][0] = __expf(sfr[nt][0] - pm0);
            sfr[nt][1] = __expf(sfr[nt][1] - pm0);
            sfr[nt][2] = __expf(sfr[nt][2] - pm1);
            sfr[nt][3] = __expf(sfr[nt][3] - pm1);
            ps0 += sfr[nt][0] + sfr[nt][1];
            ps1 += sfr[nt][2] + sfr[nt][3];
        }
        ps0 += __shfl_xor_sync(0xffffffffu, ps0, 1);
        ps0 += __shfl_xor_sync(0xffffffffu, ps0, 2);
        ps1 += __shfl_xor_sync(0xffffffffu, ps1, 1);
        ps1 += __shfl_xor_sync(0xffffffffu, ps1, 2);

        if (t == 0) {
            xm[wn * 64 + wm * 16 + g]     = pm0;
            xm[wn * 64 + wm * 16 + g + 8] = pm1;
            xl[wn * 64 + wm * 16 + g]     = ps0;
            xl[wn * 64 + wm * 16 + g + 8] = ps1;
        }
        // V_kb resident after this wait (K_{kb+1} may remain in flight)
        if (kb < qb) CP_WAIT1(); else CP_WAIT0();
        __syncthreads();

        const int r0 = wm * 16 + g;
        const float ma0 = xm[r0],    mb0 = xm[64 + r0];
        const float la0 = xl[r0],    lb0 = xl[64 + r0];
        const float ma1 = xm[r0+8],  mb1 = xm[64 + r0 + 8];
        const float la1 = xl[r0+8],  lb1 = xl[64 + r0 + 8];
        const float mt0 = fmaxf(ma0, mb0), mt1 = fmaxf(ma1, mb1);
        const float lt0 = la0 * __expf(ma0 - mt0) + lb0 * __expf(mb0 - mt0);
        const float lt1 = la1 * __expf(ma1 - mt1) + lb1 * __expf(mb1 - mt1);

        const float mnew0 = fmaxf(m0r, mt0), mnew1 = fmaxf(m1r, mt1);
        const float corr0 = __expf(m0r - mnew0), corr1 = __expf(m1r - mnew1);
        l0r = l0r * corr0 + lt0 * __expf(mt0 - mnew0);
        l1r = l1r * corr1 + lt1 * __expf(mt1 - mnew1);
        m0r = mnew0; m1r = mnew1;

        const float pf0 = __expf(pm0 - mnew0), pf1 = __expf(pm1 - mnew1);
#pragma unroll
        for (int nt = 0; nt < 4; nt++) {
            sfr[nt][0] *= pf0; sfr[nt][1] *= pf0;
            sfr[nt][2] *= pf1; sfr[nt][3] *= pf1;
        }
#pragma unroll
        for (int n8 = 0; n8 < 8; n8++) {
            o_acc[n8][0] *= corr0; o_acc[n8][1] *= corr0;
            o_acc[n8][2] *= corr1; o_acc[n8][3] *= corr1;
        }

        // P -> A fragments (bf16 hi/lo) in registers
        unsigned pa_h[2][4], pa_l[2][4];
#pragma unroll
        for (int ks2 = 0; ks2 < 2; ks2++) {
            const int ntA = 2 * ks2, ntB = 2 * ks2 + 1;
            const float p00 = sfr[ntA][0], p01 = sfr[ntA][1];
            const float p02 = sfr[ntA][2], p03 = sfr[ntA][3];
            const float p10 = sfr[ntB][0], p11 = sfr[ntB][1];
            const float p12 = sfr[ntB][2], p13 = sfr[ntB][3];
            const bf16 h00 = __float2bfloat16_rn(p00), h01 = __float2bfloat16_rn(p01);
            const bf16 h02 = __float2bfloat16_rn(p02), h03 = __float2bfloat16_rn(p03);
            const bf16 h10 = __float2bfloat16_rn(p10), h11 = __float2bfloat16_rn(p11);
            const bf16 h12 = __float2bfloat16_rn(p12), h13 = __float2bfloat16_rn(p13);
            pa_h[ks2][0] = pack_bf16(h00, h01);
            pa_h[ks2][1] = pack_bf16(h02, h03);
            pa_h[ks2][2] = pack_bf16(h10, h11);
            pa_h[ks2][3] = pack_bf16(h12, h13);
            pa_l[ks2][0] = pack_bf16(
                __float2bfloat16_rn(p00 - __bfloat162float(h00)),
                __float2bfloat16_rn(p01 - __bfloat162float(h01)));
            pa_l[ks2][1] = pack_bf16(
                __float2bfloat16_rn(p02 - __bfloat162float(h02)),
                __float2bfloat16_rn(p03 - __bfloat162float(h03)));
            pa_l[ks2][2] = pack_bf16(
                __float2bfloat16_rn(p10 - __bfloat162float(h10)),
                __float2bfloat16_rn(p11 - __bfloat162float(h11)));
            pa_l[ks2][3] = pack_bf16(
                __float2bfloat16_rn(p12 - __bfloat162float(h12)),
                __float2bfloat16_rn(p13 - __bfloat162float(h13)));
        }

        // O += P V (this warp's k-half)
#pragma unroll
        for (int ks2 = 0; ks2 < 2; ks2++) {
#pragma unroll
            for (int nc = 0; nc < 4; nc++) {
                const unsigned offv =
                    ((wn * 32 + ks2 * 16 + vkr) * AST + nc * 16 + vnc) * 2;
                unsigned rh[4], rl[4];
                ldsm4t(rh, uVh + offv);
                ldsm4t(rl, uVl + offv);
                unsigned bh0[2] = {rh[0], rh[2]}, bh1[2] = {rh[1], rh[3]};
                unsigned bl0[2] = {rl[0], rl[2]}, bl1[2] = {rl[1], rl[3]};
                mma16816(o_acc[nc*2],   pa_h[ks2], bh0);
                mma16816(o_acc[nc*2],   pa_h[ks2], bl0);
                mma16816(o_acc[nc*2],   pa_l[ks2], bh0);
                mma16816(o_acc[nc*2+1], pa_h[ks2], bh1);
                mma16816(o_acc[nc*2+1], pa_h[ks2], bl1);
                mma16816(o_acc[nc*2+1], pa_l[ks2], bh1);
            }
        }
        // no bottom sync: next top sync orders V-buffer reuse
    }
    __syncthreads();

    // cross-warp O reduction + split output (reuse K area as staging)
    float* red = (float*)(sm + AOFF_K);         // [64][66] = 16896 B
    if (wn == 1) {
#pragma unroll
        for (int n8 = 0; n8 < 8; n8++) {
            const int col = n8 * 8 + 2 * t;
            red[(wm * 16 + g)     * 66 + col]     = o_acc[n8][0];
            red[(wm * 16 + g)     * 66 + col + 1] = o_acc[n8][1];
            red[(wm * 16 + g + 8) * 66 + col]     = o_acc[n8][2];
            red[(wm * 16 + g + 8) * 66 + col + 1] = o_acc[n8][3];
        }
    }
    __syncthreads();
    if (wn == 0) {
        const float inv0 = 1.f / l0r, inv1 = 1.f / l1r;
        const size_t obase = ((size_t)(b * SEQ + qb * 64)) * HIDN + h * HD;
#pragma unroll
        for (int n8 = 0; n8 < 8; n8++) {
            const int col = n8 * 8 + 2 * t;
            const float v0 = (o_acc[n8][0] + red[(wm*16+g)*66 + col])     * inv0;
            const float v1 = (o_acc[n8][1] + red[(wm*16+g)*66 + col + 1]) * inv0;
            const float v2 = (o_acc[n8][2] + red[(wm*16+g+8)*66 + col])     * inv1;
            const float v3 = (o_acc[n8][3] + red[(wm*16+g+8)*66 + col + 1]) * inv1;
            const bf16 h0 = __float2bfloat16_rn(v0), h1 = __float2bfloat16_rn(v1);
            const bf16 h2 = __float2bfloat16_rn(v2), h3 = __float2bfloat16_rn(v3);
            const size_t i0 = obase + (size_t)(wm * 16 + g) * HIDN + col;
            const size_t i1 = obase + (size_t)(wm * 16 + g + 8) * HIDN + col;
            *(unsigned*)(goh + i0) = pack_bf16(h0, h1);
            *(unsigned*)(gol + i0) = pack_bf16(
                __float2bfloat16_rn(v0 - __bfloat162float(h0)),
                __float2bfloat16_rn(v1 - __bfloat162float(h1)));
            *(unsigned*)(goh + i1) = pack_bf16(h2, h3);
            *(unsigned*)(gol + i1) = pack_bf16(
                __float2bfloat16_rn(v2 - __bfloat162float(h2)),
                __float2bfloat16_rn(v3 - __bfloat162float(h3)));
        }
    }
}

// ---------------------------------------------------------------------------
extern "C" void kernel_launch(void* const* d_in, const int* in_sizes, int n_in,
                              void* d_out, int out_size)
{
    const float* x  = (const float*)d_in[0];
    const float* Wq = (const float*)d_in[1];
    const float* bq = (const float*)d_in[2];
    const float* Wk = (const float*)d_in[3];
    const float* bk = (const float*)d_in[4];
    const float* Wv = (const float*)d_in[5];
    const float* bv = (const float*)d_in[6];
    const float* Wo = (const float*)d_in[7];
    const float* bo = (const float*)d_in[8];
    float* out = (float*)d_out;

    bf16 *xh, *xl, *w8, *qh, *ql, *kh, *kl, *vh, *vl, *ah, *al;
    unsigned* ctr;
    cudaGetSymbolAddress((void**)&xh, g_xh);
    cudaGetSymbolAddress((void**)&xl, g_xl);
    cudaGetSymbolAddress((void**)&w8, g_w8);
    cudaGetSymbolAddress((void**)&qh, g_qh);
    cudaGetSymbolAddress((void**)&ql, g_ql);
    cudaGetSymbolAddress((void**)&kh, g_kh);
    cudaGetSymbolAddress((void**)&kl, g_kl);
    cudaGetSymbolAddress((void**)&vh, g_vh);
    cudaGetSymbolAddress((void**)&vl, g_vl);
    cudaGetSymbolAddress((void**)&ah, g_ah);
    cudaGetSymbolAddress((void**)&al, g_al);
    cudaGetSymbolAddress((void**)&ctr, g_ctr);

    cudaFuncSetAttribute(gemm_pers,
                         cudaFuncAttributeMaxDynamicSharedMemorySize, GSM_BYTES);
    cudaFuncSetAttribute(attn_mma2,
                         cudaFuncAttributeMaxDynamicSharedMemorySize, ATTN_SMEM);

    const int W2 = HIDN * HIDN;

    // One fused launch: x + Wq/Wk/Wv/Wo splits + counter reset
    split_all<<<XBLK + 4 * WBLK, 256>>>(x, Wq, Wk, Wv, Wo, xh, xl, w8);

    Job jq = { w8 + 0*W2, w8 + 1*W2, bq, qh, ql, nullptr, 0.125f };
    Job jk = { w8 + 2*W2, w8 + 3*W2, bk, kh, kl, nullptr, 1.0f };
    Job jv = { w8 + 4*W2, w8 + 5*W2, bv, vh, vl, nullptr, 1.0f };
    Job jo = { w8 + 6*W2, w8 + 7*W2, bo, nullptr, nullptr, out, 1.0f };

    // Fused QKV: 768 tiles, dynamic stealing over 296 persistent CTAs
    gemm_pers<<<296, 256, GSM_BYTES>>>(ctr + 0, 768, xh, xl, jq, jk, jv);

    attn_mma2<<<dim3(NQB, HEADS, BSZ), 256, ATTN_SMEM>>>(qh, ql, kh, kl,
                                                         vh, vl, ah, al);

    // O projection: 256 tiles
    gemm_pers<<<296, 256, GSM_BYTES>>>(ctr + 1, 256, ah, al, jo, jo, jo);
}

// round 15
// speedup vs baseline: 1.0124x; 1.0124x over previous
#include <cuda_runtime.h>
#include <cuda_bf16.h>

// Problem constants
#define BSZ   2
#define SEQ   2048
#define HIDN  1024
#define HEADS 16
#define HD    64
#define NQB   32            // SEQ / 64
#define MROWS (BSZ*SEQ)     // 4096

typedef __nv_bfloat16 bf16;

// Scratch (device globals)
__device__ bf16 g_xh[MROWS*HIDN], g_xl[MROWS*HIDN];
__device__ bf16 g_w8[8][HIDN*HIDN];       // Wq h,l  Wk h,l  Wv h,l  Wo h,l
__device__ bf16 g_qh[BSZ*HEADS*SEQ*HD], g_ql[BSZ*HEADS*SEQ*HD];
__device__ bf16 g_kh[BSZ*HEADS*SEQ*HD], g_kl[BSZ*HEADS*SEQ*HD];
__device__ bf16 g_vh[BSZ*HEADS*SEQ*HD], g_vl[BSZ*HEADS*SEQ*HD];
__device__ bf16 g_ah[MROWS*HIDN], g_al[MROWS*HIDN];   // attn out [B,S,HID]
__device__ unsigned g_ctr[2];                          // tile counters

// ===========================================================================
// helpers
// ===========================================================================
__device__ __forceinline__ unsigned smem_u32(const void* p) {
    unsigned a;
    asm("{ .reg .u64 t; cvta.to.shared.u64 t, %1; cvt.u32.u64 %0, t; }"
        : "=r"(a) : "l"(p));
    return a;
}
__device__ __forceinline__ void ldsm4(unsigned* r, unsigned addr) {
    asm volatile("ldmatrix.sync.aligned.m8n8.x4.shared.b16 {%0,%1,%2,%3}, [%4];"
                 : "=r"(r[0]), "=r"(r[1]), "=r"(r[2]), "=r"(r[3]) : "r"(addr));
}
__device__ __forceinline__ void ldsm4t(unsigned* r, unsigned addr) {
    asm volatile("ldmatrix.sync.aligned.m8n8.x4.trans.shared.b16 {%0,%1,%2,%3}, [%4];"
                 : "=r"(r[0]), "=r"(r[1]), "=r"(r[2]), "=r"(r[3]) : "r"(addr));
}
__device__ __forceinline__ void mma16816(float* c, const unsigned* a,
                                         const unsigned* b) {
    asm volatile(
        "mma.sync.aligned.m16n8k16.row.col.f32.bf16.bf16.f32 "
        "{%0,%1,%2,%3}, {%4,%5,%6,%7}, {%8,%9}, {%0,%1,%2,%3};"
        : "+f"(c[0]), "+f"(c[1]), "+f"(c[2]), "+f"(c[3])
        : "r"(a[0]), "r"(a[1]), "r"(a[2]), "r"(a[3]), "r"(b[0]), "r"(b[1]));
}
__device__ __forceinline__ unsigned pack_bf16(bf16 x, bf16 y) {
    return ((unsigned)__bfloat16_as_ushort(y) << 16) | __bfloat16_as_ushort(x);
}
#define CP_ASYNC16(dst, src) \
    asm volatile("cp.async.cg.shared.global [%0], [%1], 16;" :: "r"(dst), "l"(src))
#define CP_COMMIT() asm volatile("cp.async.commit_group;" ::: "memory")
#define CP_WAIT0()  asm volatile("cp.async.wait_group 0;" ::: "memory")

// ===========================================================================
// Fused split kernel: x + 4 weights in one launch; also resets tile counters.
// ===========================================================================
#define XBLK 2048            // (MROWS*HIDN/8)/256
#define WBLK 512             // (HIDN*HIDN/8)/256

__global__ void split_all(const float* __restrict__ x,
                          const float* __restrict__ Wq,
                          const float* __restrict__ Wk,
                          const float* __restrict__ Wv,
                          const float* __restrict__ Wo,
                          bf16* __restrict__ xh, bf16* __restrict__ xl,
                          bf16* __restrict__ w8)
{
    if (blockIdx.x == 0 && threadIdx.x == 0) { g_ctr[0] = 0; g_ctr[1] = 0; }

    const float* src;
    bf16 *hi, *lo;
    int lb;
    const int W2 = HIDN * HIDN;
    if (blockIdx.x < XBLK) {
        src = x; hi = xh; lo = xl; lb = blockIdx.x;
    } else {
        const int wi = (blockIdx.x - XBLK) / WBLK;        // 0..3
        lb = (blockIdx.x - XBLK) % WBLK;
        src = (wi == 0) ? Wq : (wi == 1) ? Wk : (wi == 2) ? Wv : Wo;
        hi = w8 + (size_t)(2 * wi) * W2;
        lo = w8 + (size_t)(2 * wi + 1) * W2;
    }

    const int base = (lb * 256 + threadIdx.x) * 2;
    float4 va = ((const float4*)src)[base];
    float4 vb = ((const float4*)src)[base + 1];
#pragma unroll
    for (int u = 0; u < 2; u++) {
        const float4 v = u ? vb : va;
        const int i = base + u;
        bf16 h0 = __float2bfloat16_rn(v.x);
        bf16 h1 = __float2bfloat16_rn(v.y);
        bf16 h2 = __float2bfloat16_rn(v.z);
        bf16 h3 = __float2bfloat16_rn(v.w);
        uint2 ho, lo2;
        ho.x = pack_bf16(h0, h1); ho.y = pack_bf16(h2, h3);
        lo2.x = pack_bf16(__float2bfloat16_rn(v.x - __bfloat162float(h0)),
                          __float2bfloat16_rn(v.y - __bfloat162float(h1)));
        lo2.y = pack_bf16(__float2bfloat16_rn(v.z - __bfloat162float(h2)),
                          __float2bfloat16_rn(v.w - __bfloat162float(h3)));
        ((uint2*)hi)[i] = ho;
        ((uint2*)lo)[i] = lo2;
    }
}

// ===========================================================================
// Persistent GEMM (unchanged from R13): tiles from global atomic counter.
// ===========================================================================
struct Job {
    const bf16* Wh; const bf16* Wl;
    const float* bias;
    bf16* Oh; bf16* Ol;
    float* Cf;
    float scl;
};

#define GST       40
#define GTILE_B   (128 * GST * 2)        // 10240 B per component tile
#define GSTAGE_B  (4 * GTILE_B)          // 40960 B
#define GSM_BYTES (2 * GSTAGE_B + 128)   // 82048 B
#define NCH2      (HIDN / 32)            // 32 chunks

__global__ __launch_bounds__(256, 2)
void gemm_pers(unsigned* ctr, int ntot,
               const bf16* __restrict__ Ah, const bf16* __restrict__ Al,
               Job j0, Job j1, Job j2)
{
    extern __shared__ char sm[];
    volatile int* slot = (volatile int*)(sm + 2 * GSTAGE_B);
    const int tid  = threadIdx.x;
    const int lane = tid & 31;
    const int wid  = tid >> 5;
    const int wm   = wid >> 2;           // 0..1
    const int wn   = wid & 3;            // 0..3

    const bf16* gsrc[4];

    auto setsrc = [&](int tile) {
        const int m  = tile >> 8;
        const int tt = tile & 255;
        const int bm = tt >> 3, bn = tt & 7;
        const Job& jb = (m == 0) ? j0 : (m == 1 ? j1 : j2);
        gsrc[0] = Ah + (size_t)bm * 128 * HIDN;
        gsrc[1] = Al + (size_t)bm * 128 * HIDN;
        gsrc[2] = jb.Wh + (size_t)bn * 128 * HIDN;
        gsrc[3] = jb.Wl + (size_t)bn * 128 * HIDN;
    };

    auto issue = [&](int kt, int buf) {
        char* st = sm + buf * GSTAGE_B;
#pragma unroll
        for (int t4 = 0; t4 < 4; t4++) {
#pragma unroll
            for (int j = 0; j < 2; j++) {
                const int ch = tid + j * 256;       // 0..511
                const int row = ch >> 2, cc = ch & 3;
                unsigned dst = smem_u32(st + t4 * GTILE_B + (row * GST + cc * 8) * 2);
                const bf16* src = gsrc[t4] + (size_t)row * HIDN + kt + cc * 8;
                CP_ASYNC16(dst, src);
            }
        }
        CP_COMMIT();
    };

    if (tid == 0) *slot = (int)atomicAdd(ctr, 1u);
    __syncthreads();
    int t = *slot;
    if (t >= ntot) return;
    setsrc(t);
    issue(0, 0);

    const int fr = lane & 15;
    const int fc = (lane >> 4) << 3;
    const int g = lane >> 2, tq = lane & 3;

    while (true) {
        float acc[4][4][4];
#pragma unroll
        for (int i = 0; i < 4; i++)
#pragma unroll
            for (int j = 0; j < 4; j++)
#pragma unroll
                for (int k = 0; k < 4; k++) acc[i][j][k] = 0.f;

        int tn = ntot;
        for (int c = 0; c < NCH2; c++) {
            CP_WAIT0();
            __syncthreads();
            if (c == NCH2 - 2 && tid == 0) *slot = (int)atomicAdd(ctr, 1u);
            if (c < NCH2 - 1) {
                issue((c + 1) * 32, (c + 1) & 1);
            } else {
                tn = *slot;
                if (tn < ntot) { setsrc(tn); issue(0, 0); }
            }

            const unsigned sb = smem_u32(sm) + (c & 1) * GSTAGE_B;
            const unsigned uAh = sb, uAl = sb + GTILE_B;
            const unsigned uWh = sb + 2 * GTILE_B, uWl = sb + 3 * GTILE_B;

#pragma unroll
            for (int ks = 0; ks < 2; ks++) {
                const int kcol = ks * 16 + fc;
                unsigned ah[4][4], al[4][4], bh[4][2], bl[4][2];
#pragma unroll
                for (int mt = 0; mt < 4; mt++) {
                    const unsigned off = ((wm * 64 + mt * 16 + fr) * GST + kcol) * 2;
                    ldsm4(ah[mt], uAh + off);
                    ldsm4(al[mt], uAl + off);
                }
#pragma unroll
                for (int ntp = 0; ntp < 2; ntp++) {
                    const unsigned off = ((wn * 32 + ntp * 16 + fr) * GST + kcol) * 2;
                    unsigned r[4];
                    ldsm4(r, uWh + off);
                    bh[2*ntp][0] = r[0]; bh[2*ntp+1][0] = r[1];
                    bh[2*ntp][1] = r[2]; bh[2*ntp+1][1] = r[3];
                    ldsm4(r, uWl + off);
                    bl[2*ntp][0] = r[0]; bl[2*ntp+1][0] = r[1];
                    bl[2*ntp][1] = r[2]; bl[2*ntp+1][1] = r[3];
                }
#pragma unroll
                for (int mt = 0; mt < 4; mt++)
#pragma unroll
                    for (int nt = 0; nt < 4; nt++) {
                        mma16816(acc[mt][nt], ah[mt], bh[nt]);
                        mma16816(acc[mt][nt], ah[mt], bl[nt]);
                        mma16816(acc[mt][nt], al[mt], bh[nt]);
                    }
            }
        }

        {
            const int m  = t >> 8;
            const int tt = t & 255;
            const int bm = tt >> 3, bn = tt & 7;
            const Job& jb = (m == 0) ? j0 : (m == 1 ? j1 : j2);
#pragma unroll
            for (int mt = 0; mt < 4; mt++) {
#pragma unroll
                for (int nt = 0; nt < 4; nt++) {
                    const int n = bn * 128 + wn * 32 + nt * 8 + 2 * tq;
                    const float2 bi = *(const float2*)(jb.bias + n);
                    const int m0 = bm * 128 + wm * 64 + mt * 16 + g;
#pragma unroll
                    for (int half = 0; half < 2; half++) {
                        const int mr = m0 + half * 8;
                        float vx = (acc[mt][nt][half * 2 + 0] + bi.x) * jb.scl;
                        float vy = (acc[mt][nt][half * 2 + 1] + bi.y) * jb.scl;
                        if (jb.Cf) {
                            *(float2*)(jb.Cf + (size_t)mr * HIDN + n) =
                                make_float2(vx, vy);
                        } else {
                            const int b = mr >> 11, s = mr & 2047;
                            const int hh = n >> 6, d = n & 63;
                            const size_t idx =
                                (((size_t)(b * HEADS + hh)) * SEQ + s) * HD + d;
                            bf16 h0 = __float2bfloat16_rn(vx);
                            bf16 h1 = __float2bfloat16_rn(vy);
                            *(unsigned*)(jb.Oh + idx) = pack_bf16(h0, h1);
                            *(unsigned*)(jb.Ol + idx) = pack_bf16(
                                __float2bfloat16_rn(vx - __bfloat162float(h0)),
                                __float2bfloat16_rn(vy - __bfloat162float(h1)));
                        }
                    }
                }
            }
        }

        if (tn >= ntot) return;
        t = tn;
    }
}

// ===========================================================================
// Block-causal flash attention — DEFERRED HALF-MERGE:
// each wn half (k-cols wn*32..wn*32+31 of every block) keeps a private
// online-softmax state (m, l, O); halves merge ONCE at the end.
// One __syncthreads per iteration (KV stage reuse; also orders cp.async
// visibility since PV(kb-1) precedes it).
// ===========================================================================
#define AST     72
#define ATILE_B (64 * AST * 2)            // 9216 B
#define AOFF_STAGE 18432
#define AOFF_XM  (AOFF_STAGE + 2 * 4 * ATILE_B)   // 92160 (final-merge m/l)
#define ATTN_SMEM (AOFF_XM + 2048)        // 94208 B -> 2 CTAs/SM

__global__ __launch_bounds__(256, 2)
void attn_mma2(const bf16* __restrict__ gqh, const bf16* __restrict__ gql,
               const bf16* __restrict__ gkh, const bf16* __restrict__ gkl,
               const bf16* __restrict__ gvh, const bf16* __restrict__ gvl,
               bf16* __restrict__ goh, bf16* __restrict__ gol)
{
    extern __shared__ char sm[];
    const int qb = NQB - 1 - blockIdx.x;
    const int h = blockIdx.y, b = blockIdx.z;
    const int tid  = threadIdx.x;
    const int lane = tid & 31;
    const int wid  = tid >> 5;
    const int wm   = wid >> 1;
    const int wn   = wid & 1;
    const int fr = lane & 15, fc = (lane >> 4) << 3;
    const int g  = lane >> 2, t = lane & 3;
    const int vkr = ((lane >> 4) << 3) + (lane & 7);
    const int vnc = ((lane >> 3) & 1) << 3;

    const size_t hb = ((size_t)(b * HEADS + h)) * SEQ * HD;
    const bf16* src_k[4];
    src_k[0] = gkh + hb; src_k[1] = gkl + hb;
    src_k[2] = gvh + hb; src_k[3] = gvl + hb;

    auto issueKV = [&](int kb) {
        char* st = sm + AOFF_STAGE + (kb & 1) * 4 * ATILE_B;
        const size_t koff = (size_t)kb * 64 * HD;
#pragma unroll
        for (int t4 = 0; t4 < 4; t4++) {
#pragma unroll
            for (int j = 0; j < 2; j++) {
                const int ch = tid + j * 256;
                const int row = ch >> 3, cc = ch & 7;
                unsigned dst = smem_u32(st + t4 * ATILE_B + (row * AST + cc * 8) * 2);
                CP_ASYNC16(dst, src_k[t4] + koff + row * HD + cc * 8);
            }
        }
        CP_COMMIT();
    };

    issueKV(0);

    {
        const bf16* qh = gqh + hb + (size_t)qb * 64 * HD;
        const bf16* ql = gql + hb + (size_t)qb * 64 * HD;
#pragma unroll
        for (int j = 0; j < 2; j++) {
            const int ch = tid + j * 256;
            const int row = ch >> 3, cc = ch & 7;
            *(uint4*)(sm + (row * AST + cc * 8) * 2) =
                *(const uint4*)(qh + row * HD + cc * 8);
            *(uint4*)(sm + ATILE_B + (row * AST + cc * 8) * 2) =
                *(const uint4*)(ql + row * HD + cc * 8);
        }
    }

    const unsigned uQh = smem_u32(sm), uQl = uQh + ATILE_B;

    float o_acc[8][4];
#pragma unroll
    for (int i = 0; i < 8; i++)
#pragma unroll
        for (int j = 0; j < 4; j++) o_acc[i][j] = 0.f;
    // private per-half online-softmax state
    float m0r = -1e30f, m1r = -1e30f, l0r = 0.f, l1r = 0.f;

    for (int kb = 0; kb <= qb; kb++) {
        CP_WAIT0();               // stage kb resident
        __syncthreads();          // all warps past PV(kb-1): other buffer free
        if (kb < qb) issueKV(kb + 1);

        const unsigned us = smem_u32(sm) + AOFF_STAGE + (kb & 1) * 4 * ATILE_B;
        const unsigned uKh = us, uKl = us + ATILE_B;
        const unsigned uVh = us + 2 * ATILE_B, uVl = us + 3 * ATILE_B;

        float sfr[4][4];
#pragma unroll
        for (int i = 0; i < 4; i++)
#pragma unroll
            for (int j = 0; j < 4; j++) sfr[i][j] = 0.f;

#pragma unroll
        for (int ks = 0; ks < 4; ks++) {
            const int kcol = ks * 16 + fc;
            unsigned qa_h[4], qa_l[4];
            const unsigned offa = ((wm * 16 + fr) * AST + kcol) * 2;
            ldsm4(qa_h, uQh + offa);
            ldsm4(qa_l, uQl + offa);
#pragma unroll
            for (int ntp = 0; ntp < 2; ntp++) {
                const unsigned offb = ((wn * 32 + ntp * 16 + fr) * AST + kcol) * 2;
                unsigned rh[4], rl[4];
                ldsm4(rh, uKh + offb);
                ldsm4(rl, uKl + offb);
                unsigned bh0[2] = {rh[0], rh[2]}, bh1[2] = {rh[1], rh[3]};
                unsigned bl0[2] = {rl[0], rl[2]}, bl1[2] = {rl[1], rl[3]};
                mma16816(sfr[2*ntp],   qa_h, bh0);
                mma16816(sfr[2*ntp],   qa_h, bl0);
                mma16816(sfr[2*ntp],   qa_l, bh0);
                mma16816(sfr[2*ntp+1], qa_h, bh1);
                mma16816(sfr[2*ntp+1], qa_h, bl1);
                mma16816(sfr[2*ntp+1], qa_l, bh1);
            }
        }

        // private (per-half) online softmax: quad-shfl reduce only
        float pm0 = sfr[0][0], pm1 = sfr[0][2];
#pragma unroll
        for (int nt = 0; nt < 4; nt++) {
            pm0 = fmaxf(pm0, fmaxf(sfr[nt][0], sfr[nt][1]));
            pm1 = fmaxf(pm1, fmaxf(sfr[nt][2], sfr[nt][3]));
        }
        pm0 = fmaxf(pm0, __shfl_xor_sync(0xffffffffu, pm0, 1));
        pm0 = fmaxf(pm0, __shfl_xor_sync(0xffffffffu, pm0, 2));
        pm1 = fmaxf(pm1, __shfl_xor_sync(0xffffffffu, pm1, 1));
        pm1 = fmaxf(pm1, __shfl_xor_sync(0xffffffffu, pm1, 2));

        const float mnew0 = fmaxf(m0r, pm0), mnew1 = fmaxf(m1r, pm1);
        const float corr0 = __expf(m0r - mnew0), corr1 = __expf(m1r - mnew1);
        const float pf0 = __expf(pm0 - mnew0), pf1 = __expf(pm1 - mnew1);

        float ps0 = 0.f, ps1 = 0.f;
#pragma unroll
        for (int nt = 0; nt < 4; nt++) {
            sfr[nt][0] = __expf(sfr[nt][0] - pm0);
            sfr[nt][1] = __expf(sfr[nt][1] - pm0);
            sfr[nt][2] = __expf(sfr[nt][2] - pm1);
            sfr[nt][3] = __expf(sfr[nt][3] - pm1);
            ps0 += sfr[nt][0] + sfr[nt][1];
            ps1 += sfr[nt][2] + sfr[nt][3];
        }
        ps0 += __shfl_xor_sync(0xffffffffu, ps0, 1);
        ps0 += __shfl_xor_sync(0xffffffffu, ps0, 2);
        ps1 += __shfl_xor_sync(0xffffffffu, ps1, 1);
        ps1 += __shfl_xor_sync(0xffffffffu, ps1, 2);

        l0r = l0r * corr0 + ps0 * pf0;
        l1r = l1r * corr1 + ps1 * pf1;
        m0r = mnew0; m1r = mnew1;

#pragma unroll
        for (int nt = 0; nt < 4; nt++) {
            sfr[nt][0] *= pf0; sfr[nt][1] *= pf0;
            sfr[nt][2] *= pf1; sfr[nt][3] *= pf1;
        }
#pragma unroll
        for (int n8 = 0; n8 < 8; n8++) {
            o_acc[n8][0] *= corr0; o_acc[n8][1] *= corr0;
            o_acc[n8][2] *= corr1; o_acc[n8][3] *= corr1;
        }

        // P -> A fragments (bf16 hi/lo) in registers
        unsigned pa_h[2][4], pa_l[2][4];
#pragma unroll
        for (int ks2 = 0; ks2 < 2; ks2++) {
            const int ntA = 2 * ks2, ntB = 2 * ks2 + 1;
            const float p00 = sfr[ntA][0], p01 = sfr[ntA][1];
            const float p02 = sfr[ntA][2], p03 = sfr[ntA][3];
            const float p10 = sfr[ntB][0], p11 = sfr[ntB][1];
            const float p12 = sfr[ntB][2], p13 = sfr[ntB][3];
            const bf16 h00 = __float2bfloat16_rn(p00), h01 = __float2bfloat16_rn(p01);
            const bf16 h02 = __float2bfloat16_rn(p02), h03 = __float2bfloat16_rn(p03);
            const bf16 h10 = __float2bfloat16_rn(p10), h11 = __float2bfloat16_rn(p11);
            const bf16 h12 = __float2bfloat16_rn(p12), h13 = __float2bfloat16_rn(p13);
            pa_h[ks2][0] = pack_bf16(h00, h01);
            pa_h[ks2][1] = pack_bf16(h02, h03);
            pa_h[ks2][2] = pack_bf16(h10, h11);
            pa_h[ks2][3] = pack_bf16(h12, h13);
            pa_l[ks2][0] = pack_bf16(
                __float2bfloat16_rn(p00 - __bfloat162float(h00)),
                __float2bfloat16_rn(p01 - __bfloat162float(h01)));
            pa_l[ks2][1] = pack_bf16(
                __float2bfloat16_rn(p02 - __bfloat162float(h02)),
                __float2bfloat16_rn(p03 - __bfloat162float(h03)));
            pa_l[ks2][2] = pack_bf16(
                __float2bfloat16_rn(p10 - __bfloat162float(h10)),
                __float2bfloat16_rn(p11 - __bfloat162float(h11)));
            pa_l[ks2][3] = pack_bf16(
                __float2bfloat16_rn(p12 - __bfloat162float(h12)),
                __float2bfloat16_rn(p13 - __bfloat162float(h13)));
        }

        // O += P V (this warp's k-half)
#pragma unroll
        for (int ks2 = 0; ks2 < 2; ks2++) {
#pragma unroll
            for (int nc = 0; nc < 4; nc++) {
                const unsigned offv =
                    ((wn * 32 + ks2 * 16 + vkr) * AST + nc * 16 + vnc) * 2;
                unsigned rh[4], rl[4];
                ldsm4t(rh, uVh + offv);
                ldsm4t(rl, uVl + offv);
                unsigned bh0[2] = {rh[0], rh[2]}, bh1[2] = {rh[1], rh[3]};
                unsigned bl0[2] = {rl[0], rl[2]}, bl1[2] = {rl[1], rl[3]};
                mma16816(o_acc[nc*2],   pa_h[ks2], bh0);
                mma16816(o_acc[nc*2],   pa_h[ks2], bl0);
                mma16816(o_acc[nc*2],   pa_l[ks2], bh0);
                mma16816(o_acc[nc*2+1], pa_h[ks2], bh1);
                mma16816(o_acc[nc*2+1], pa_h[ks2], bl1);
                mma16816(o_acc[nc*2+1], pa_l[ks2], bh1);
            }
        }
        // single sync per iteration (top of next iteration)
    }
    __syncthreads();   // all PV done before staging reuse

    // Final half-merge + output.
    // wn=1 publishes raw O_b plus its per-row (m_b, l_b); wn=0 merges:
    //   m = max(m_a, m_b); O = O_a e^{m_a-m} + O_b e^{m_b-m}; l likewise.
    float* red = (float*)(sm + AOFF_STAGE);     // [64][66]
    float* mB  = (float*)(sm + AOFF_XM);        // [64]
    float* lB  = mB + 64;                       // [64]
    if (wn == 1) {
#pragma unroll
        for (int n8 = 0; n8 < 8; n8++) {
            const int col = n8 * 8 + 2 * t;
            red[(wm * 16 + g)     * 66 + col]     = o_acc[n8][0];
            red[(wm * 16 + g)     * 66 + col + 1] = o_acc[n8][1];
            red[(wm * 16 + g + 8) * 66 + col]     = o_acc[n8][2];
            red[(wm * 16 + g + 8) * 66 + col + 1] = o_acc[n8][3];
        }
        if (t == 0) {
            mB[wm * 16 + g]     = m0r;  lB[wm * 16 + g]     = l0r;
            mB[wm * 16 + g + 8] = m1r;  lB[wm * 16 + g + 8] = l1r;
        }
    }
    __syncthreads();
    if (wn == 0) {
        const int r0 = wm * 16 + g;
        const float mb0 = mB[r0],     lb0 = lB[r0];
        const float mb1 = mB[r0 + 8], lb1 = lB[r0 + 8];
        const float mf0 = fmaxf(m0r, mb0), mf1 = fmaxf(m1r, mb1);
        const float sA0 = __expf(m0r - mf0), sB0 = __expf(mb0 - mf0);
        const float sA1 = __expf(m1r - mf1), sB1 = __expf(mb1 - mf1);
        const float inv0 = 1.f / (l0r * sA0 + lb0 * sB0);
        const float inv1 = 1.f / (l1r * sA1 + lb1 * sB1);
        const size_t obase = ((size_t)(b * SEQ + qb * 64)) * HIDN + h * HD;
#pragma unroll
        for (int n8 = 0; n8 < 8; n8++) {
            const int col = n8 * 8 + 2 * t;
            const float v0 = (o_acc[n8][0] * sA0 + red[r0*66 + col]     * sB0) * inv0;
            const float v1 = (o_acc[n8][1] * sA0 + red[r0*66 + col + 1] * sB0) * inv0;
            const float v2 = (o_acc[n8][2] * sA1 + red[(r0+8)*66 + col]     * sB1) * inv1;
            const float v3 = (o_acc[n8][3] * sA1 + red[(r0+8)*66 + col + 1] * sB1) * inv1;
            const bf16 h0 = __float2bfloat16_rn(v0), h1 = __float2bfloat16_rn(v1);
            const bf16 h2 = __float2bfloat16_rn(v2), h3 = __float2bfloat16_rn(v3);
            const size_t i0 = obase + (size_t)r0 * HIDN + col;
            const size_t i1 = obase + (size_t)(r0 + 8) * HIDN + col;
            *(unsigned*)(goh + i0) = pack_bf16(h0, h1);
            *(unsigned*)(gol + i0) = pack_bf16(
                __float2bfloat16_rn(v0 - __bfloat162float(h0)),
                __float2bfloat16_rn(v1 - __bfloat162float(h1)));
            *(unsigned*)(goh + i1) = pack_bf16(h2, h3);
            *(unsigned*)(gol + i1) = pack_bf16(
                __float2bfloat16_rn(v2 - __bfloat162float(h2)),
                __float2bfloat16_rn(v3 - __bfloat162float(h3)));
        }
    }
}

// ---------------------------------------------------------------------------
extern "C" void kernel_launch(void* const* d_in, const int* in_sizes, int n_in,
                              void* d_out, int out_size)
{
    const float* x  = (const float*)d_in[0];
    const float* Wq = (const float*)d_in[1];
    const float* bq = (const float*)d_in[2];
    const float* Wk = (const float*)d_in[3];
    const float* bk = (const float*)d_in[4];
    const float* Wv = (const float*)d_in[5];
    const float* bv = (const float*)d_in[6];
    const float* Wo = (const float*)d_in[7];
    const float* bo = (const float*)d_in[8];
    float* out = (float*)d_out;

    bf16 *xh, *xl, *w8, *qh, *ql, *kh, *kl, *vh, *vl, *ah, *al;
    unsigned* ctr;
    cudaGetSymbolAddress((void**)&xh, g_xh);
    cudaGetSymbolAddress((void**)&xl, g_xl);
    cudaGetSymbolAddress((void**)&w8, g_w8);
    cudaGetSymbolAddress((void**)&qh, g_qh);
    cudaGetSymbolAddress((void**)&ql, g_ql);
    cudaGetSymbolAddress((void**)&kh, g_kh);
    cudaGetSymbolAddress((void**)&kl, g_kl);
    cudaGetSymbolAddress((void**)&vh, g_vh);
    cudaGetSymbolAddress((void**)&vl, g_vl);
    cudaGetSymbolAddress((void**)&ah, g_ah);
    cudaGetSymbolAddress((void**)&al, g_al);
    cudaGetSymbolAddress((void**)&ctr, g_ctr);

    cudaFuncSetAttribute(gemm_pers,
                         cudaFuncAttributeMaxDynamicSharedMemorySize, GSM_BYTES);
    cudaFuncSetAttribute(attn_mma2,
                         cudaFuncAttributeMaxDynamicSharedMemorySize, ATTN_SMEM);

    const int W2 = HIDN * HIDN;

    // One fused launch: x + Wq/Wk/Wv/Wo splits + counter reset
    split_all<<<XBLK + 4 * WBLK, 256>>>(x, Wq, Wk, Wv, Wo, xh, xl, w8);

    Job jq = { w8 + 0*W2, w8 + 1*W2, bq, qh, ql, nullptr, 0.125f };
    Job jk = { w8 + 2*W2, w8 + 3*W2, bk, kh, kl, nullptr, 1.0f };
    Job jv = { w8 + 4*W2, w8 + 5*W2, bv, vh, vl, nullptr, 1.0f };
    Job jo = { w8 + 6*W2, w8 + 7*W2, bo, nullptr, nullptr, out, 1.0f };

    // Fused QKV: 768 tiles, dynamic stealing over 296 persistent CTAs
    gemm_pers<<<296, 256, GSM_BYTES>>>(ctr + 0, 768, xh, xl, jq, jk, jv);

    attn_mma2<<<dim3(NQB, HEADS, BSZ), 256, ATTN_SMEM>>>(qh, ql, kh, kl,
                                                         vh, vl, ah, al);

    // O projection: 256 tiles
    gemm_pers<<<296, 256, GSM_BYTES>>>(ctr + 1, 256, ah, al, jo, jo, jo);
}

// round 16
// speedup vs baseline: 1.0680x; 1.0549x over previous
#include <cuda_runtime.h>
#include <cuda_bf16.h>

// Problem constants
#define BSZ   2
#define SEQ   2048
#define HIDN  1024
#define HEADS 16
#define HD    64
#define NQB   32            // SEQ / 64
#define MROWS (BSZ*SEQ)     // 4096

typedef __nv_bfloat16 bf16;

// Scratch (device globals)
__device__ bf16 g_xh[MROWS*HIDN], g_xl[MROWS*HIDN];
__device__ bf16 g_w8[8][HIDN*HIDN];       // Wq h,l  Wk h,l  Wv h,l  Wo h,l
__device__ bf16 g_qh[BSZ*HEADS*SEQ*HD], g_ql[BSZ*HEADS*SEQ*HD];
__device__ bf16 g_kh[BSZ*HEADS*SEQ*HD], g_kl[BSZ*HEADS*SEQ*HD];
__device__ bf16 g_vh[BSZ*HEADS*SEQ*HD], g_vl[BSZ*HEADS*SEQ*HD];
__device__ bf16 g_ah[MROWS*HIDN], g_al[MROWS*HIDN];   // attn out [B,S,HID]
__device__ unsigned g_ctr[2];                          // tile counters

// ===========================================================================
// helpers
// ===========================================================================
__device__ __forceinline__ unsigned smem_u32(const void* p) {
    unsigned a;
    asm("{ .reg .u64 t; cvta.to.shared.u64 t, %1; cvt.u32.u64 %0, t; }"
        : "=r"(a) : "l"(p));
    return a;
}
__device__ __forceinline__ void ldsm4(unsigned* r, unsigned addr) {
    asm volatile("ldmatrix.sync.aligned.m8n8.x4.shared.b16 {%0,%1,%2,%3}, [%4];"
                 : "=r"(r[0]), "=r"(r[1]), "=r"(r[2]), "=r"(r[3]) : "r"(addr));
}
__device__ __forceinline__ void ldsm4t(unsigned* r, unsigned addr) {
    asm volatile("ldmatrix.sync.aligned.m8n8.x4.trans.shared.b16 {%0,%1,%2,%3}, [%4];"
                 : "=r"(r[0]), "=r"(r[1]), "=r"(r[2]), "=r"(r[3]) : "r"(addr));
}
__device__ __forceinline__ void mma16816(float* c, const unsigned* a,
                                         const unsigned* b) {
    asm volatile(
        "mma.sync.aligned.m16n8k16.row.col.f32.bf16.bf16.f32 "
        "{%0,%1,%2,%3}, {%4,%5,%6,%7}, {%8,%9}, {%0,%1,%2,%3};"
        : "+f"(c[0]), "+f"(c[1]), "+f"(c[2]), "+f"(c[3])
        : "r"(a[0]), "r"(a[1]), "r"(a[2]), "r"(a[3]), "r"(b[0]), "r"(b[1]));
}
__device__ __forceinline__ unsigned pack_bf16(bf16 x, bf16 y) {
    return ((unsigned)__bfloat16_as_ushort(y) << 16) | __bfloat16_as_ushort(x);
}
#define CP_ASYNC16(dst, src) \
    asm volatile("cp.async.cg.shared.global [%0], [%1], 16;" :: "r"(dst), "l"(src))
#define CP_COMMIT() asm volatile("cp.async.commit_group;" ::: "memory")
#define CP_WAIT0()  asm volatile("cp.async.wait_group 0;" ::: "memory")

// ===========================================================================
// Fused split kernel: x + 4 weights in one launch; also resets tile counters.
// ===========================================================================
#define XBLK 2048            // (MROWS*HIDN/8)/256
#define WBLK 512             // (HIDN*HIDN/8)/256

__global__ void split_all(const float* __restrict__ x,
                          const float* __restrict__ Wq,
                          const float* __restrict__ Wk,
                          const float* __restrict__ Wv,
                          const float* __restrict__ Wo,
                          bf16* __restrict__ xh, bf16* __restrict__ xl,
                          bf16* __restrict__ w8)
{
    if (blockIdx.x == 0 && threadIdx.x == 0) { g_ctr[0] = 0; g_ctr[1] = 0; }

    const float* src;
    bf16 *hi, *lo;
    int lb;
    const int W2 = HIDN * HIDN;
    if (blockIdx.x < XBLK) {
        src = x; hi = xh; lo = xl; lb = blockIdx.x;
    } else {
        const int wi = (blockIdx.x - XBLK) / WBLK;        // 0..3
        lb = (blockIdx.x - XBLK) % WBLK;
        src = (wi == 0) ? Wq : (wi == 1) ? Wk : (wi == 2) ? Wv : Wo;
        hi = w8 + (size_t)(2 * wi) * W2;
        lo = w8 + (size_t)(2 * wi + 1) * W2;
    }

    const int base = (lb * 256 + threadIdx.x) * 2;
    float4 va = ((const float4*)src)[base];
    float4 vb = ((const float4*)src)[base + 1];
#pragma unroll
    for (int u = 0; u < 2; u++) {
        const float4 v = u ? vb : va;
        const int i = base + u;
        bf16 h0 = __float2bfloat16_rn(v.x);
        bf16 h1 = __float2bfloat16_rn(v.y);
        bf16 h2 = __float2bfloat16_rn(v.z);
        bf16 h3 = __float2bfloat16_rn(v.w);
        uint2 ho, lo2;
        ho.x = pack_bf16(h0, h1); ho.y = pack_bf16(h2, h3);
        lo2.x = pack_bf16(__float2bfloat16_rn(v.x - __bfloat162float(h0)),
                          __float2bfloat16_rn(v.y - __bfloat162float(h1)));
        lo2.y = pack_bf16(__float2bfloat16_rn(v.z - __bfloat162float(h2)),
                          __float2bfloat16_rn(v.w - __bfloat162float(h3)));
        ((uint2*)hi)[i] = ho;
        ((uint2*)lo)[i] = lo2;
    }
}

// ===========================================================================
// Persistent GEMM (unchanged from R13): tiles from global atomic counter.
// ===========================================================================
struct Job {
    const bf16* Wh; const bf16* Wl;
    const float* bias;
    bf16* Oh; bf16* Ol;
    float* Cf;
    float scl;
};

#define GST       40
#define GTILE_B   (128 * GST * 2)        // 10240 B per component tile
#define GSTAGE_B  (4 * GTILE_B)          // 40960 B
#define GSM_BYTES (2 * GSTAGE_B + 128)   // 82048 B
#define NCH2      (HIDN / 32)            // 32 chunks

__global__ __launch_bounds__(256, 2)
void gemm_pers(unsigned* ctr, int ntot,
               const bf16* __restrict__ Ah, const bf16* __restrict__ Al,
               Job j0, Job j1, Job j2)
{
    extern __shared__ char sm[];
    volatile int* slot = (volatile int*)(sm + 2 * GSTAGE_B);
    const int tid  = threadIdx.x;
    const int lane = tid & 31;
    const int wid  = tid >> 5;
    const int wm   = wid >> 2;           // 0..1
    const int wn   = wid & 3;            // 0..3

    const bf16* gsrc[4];

    auto setsrc = [&](int tile) {
        const int m  = tile >> 8;
        const int tt = tile & 255;
        const int bm = tt >> 3, bn = tt & 7;
        const Job& jb = (m == 0) ? j0 : (m == 1 ? j1 : j2);
        gsrc[0] = Ah + (size_t)bm * 128 * HIDN;
        gsrc[1] = Al + (size_t)bm * 128 * HIDN;
        gsrc[2] = jb.Wh + (size_t)bn * 128 * HIDN;
        gsrc[3] = jb.Wl + (size_t)bn * 128 * HIDN;
    };

    auto issue = [&](int kt, int buf) {
        char* st = sm + buf * GSTAGE_B;
#pragma unroll
        for (int t4 = 0; t4 < 4; t4++) {
#pragma unroll
            for (int j = 0; j < 2; j++) {
                const int ch = tid + j * 256;       // 0..511
                const int row = ch >> 2, cc = ch & 3;
                unsigned dst = smem_u32(st + t4 * GTILE_B + (row * GST + cc * 8) * 2);
                const bf16* src = gsrc[t4] + (size_t)row * HIDN + kt + cc * 8;
                CP_ASYNC16(dst, src);
            }
        }
        CP_COMMIT();
    };

    if (tid == 0) *slot = (int)atomicAdd(ctr, 1u);
    __syncthreads();
    int t = *slot;
    if (t >= ntot) return;
    setsrc(t);
    issue(0, 0);

    const int fr = lane & 15;
    const int fc = (lane >> 4) << 3;
    const int g = lane >> 2, tq = lane & 3;

    while (true) {
        float acc[4][4][4];
#pragma unroll
        for (int i = 0; i < 4; i++)
#pragma unroll
            for (int j = 0; j < 4; j++)
#pragma unroll
                for (int k = 0; k < 4; k++) acc[i][j][k] = 0.f;

        int tn = ntot;
        for (int c = 0; c < NCH2; c++) {
            CP_WAIT0();
            __syncthreads();
            if (c == NCH2 - 2 && tid == 0) *slot = (int)atomicAdd(ctr, 1u);
            if (c < NCH2 - 1) {
                issue((c + 1) * 32, (c + 1) & 1);
            } else {
                tn = *slot;
                if (tn < ntot) { setsrc(tn); issue(0, 0); }
            }

            const unsigned sb = smem_u32(sm) + (c & 1) * GSTAGE_B;
            const unsigned uAh = sb, uAl = sb + GTILE_B;
            const unsigned uWh = sb + 2 * GTILE_B, uWl = sb + 3 * GTILE_B;

#pragma unroll
            for (int ks = 0; ks < 2; ks++) {
                const int kcol = ks * 16 + fc;
                unsigned ah[4][4], al[4][4], bh[4][2], bl[4][2];
#pragma unroll
                for (int mt = 0; mt < 4; mt++) {
                    const unsigned off = ((wm * 64 + mt * 16 + fr) * GST + kcol) * 2;
                    ldsm4(ah[mt], uAh + off);
                    ldsm4(al[mt], uAl + off);
                }
#pragma unroll
                for (int ntp = 0; ntp < 2; ntp++) {
                    const unsigned off = ((wn * 32 + ntp * 16 + fr) * GST + kcol) * 2;
                    unsigned r[4];
                    ldsm4(r, uWh + off);
                    bh[2*ntp][0] = r[0]; bh[2*ntp+1][0] = r[1];
                    bh[2*ntp][1] = r[2]; bh[2*ntp+1][1] = r[3];
                    ldsm4(r, uWl + off);
                    bl[2*ntp][0] = r[0]; bl[2*ntp+1][0] = r[1];
                    bl[2*ntp][1] = r[2]; bl[2*ntp+1][1] = r[3];
                }
#pragma unroll
                for (int mt = 0; mt < 4; mt++)
#pragma unroll
                    for (int nt = 0; nt < 4; nt++) {
                        mma16816(acc[mt][nt], ah[mt], bh[nt]);
                        mma16816(acc[mt][nt], ah[mt], bl[nt]);
                        mma16816(acc[mt][nt], al[mt], bh[nt]);
                    }
            }
        }

        {
            const int m  = t >> 8;
            const int tt = t & 255;
            const int bm = tt >> 3, bn = tt & 7;
            const Job& jb = (m == 0) ? j0 : (m == 1 ? j1 : j2);
#pragma unroll
            for (int mt = 0; mt < 4; mt++) {
#pragma unroll
                for (int nt = 0; nt < 4; nt++) {
                    const int n = bn * 128 + wn * 32 + nt * 8 + 2 * tq;
                    const float2 bi = *(const float2*)(jb.bias + n);
                    const int m0 = bm * 128 + wm * 64 + mt * 16 + g;
#pragma unroll
                    for (int half = 0; half < 2; half++) {
                        const int mr = m0 + half * 8;
                        float vx = (acc[mt][nt][half * 2 + 0] + bi.x) * jb.scl;
                        float vy = (acc[mt][nt][half * 2 + 1] + bi.y) * jb.scl;
                        if (jb.Cf) {
                            *(float2*)(jb.Cf + (size_t)mr * HIDN + n) =
                                make_float2(vx, vy);
                        } else {
                            const int b = mr >> 11, s = mr & 2047;
                            const int hh = n >> 6, d = n & 63;
                            const size_t idx =
                                (((size_t)(b * HEADS + hh)) * SEQ + s) * HD + d;
                            bf16 h0 = __float2bfloat16_rn(vx);
                            bf16 h1 = __float2bfloat16_rn(vy);
                            *(unsigned*)(jb.Oh + idx) = pack_bf16(h0, h1);
                            *(unsigned*)(jb.Ol + idx) = pack_bf16(
                                __float2bfloat16_rn(vx - __bfloat162float(h0)),
                                __float2bfloat16_rn(vy - __bfloat162float(h1)));
                        }
                    }
                }
            }
        }

        if (tn >= ntot) return;
        t = tn;
    }
}

// ===========================================================================
// Block-causal flash attention — TWO INDEPENDENT WARP-GROUPS per CTA.
// Group g (4 warps, 128 threads) processes kb = g, g+2, ... with private
// online-softmax state (2^x domain; log2e folded into Q scale). Groups sync
// only via named barriers; merged once at the end. K/V committed separately
// so K(kb+2) loads under softmax+PV and V(kb+2) under the next S phase.
// ===========================================================================
#define AST     72
#define ATILE_B (64 * AST * 2)            // 9216 B
#define GRP_STAGE (4 * ATILE_B)           // 36864 B per group
#define AOFF_STAGE 18432                  // after Qh, Ql
#define AOFF_XM  (AOFF_STAGE + 2 * GRP_STAGE)     // 92160 (final-merge m/l)
#define ATTN_SMEM (AOFF_XM + 2048)        // 94208 B -> 2 CTAs/SM

#define BARG() asm volatile("bar.sync %0, 128;" :: "r"(grp + 1) : "memory")

__global__ __launch_bounds__(256, 2)
void attn_mma2(const bf16* __restrict__ gqh, const bf16* __restrict__ gql,
               const bf16* __restrict__ gkh, const bf16* __restrict__ gkl,
               const bf16* __restrict__ gvh, const bf16* __restrict__ gvl,
               bf16* __restrict__ goh, bf16* __restrict__ gol)
{
    extern __shared__ char sm[];
    const int qb = NQB - 1 - blockIdx.x;
    const int h = blockIdx.y, b = blockIdx.z;
    const int tid  = threadIdx.x;
    const int lane = tid & 31;
    const int wid  = tid >> 5;
    const int grp  = wid >> 2;              // 0..1 (warp-group)
    const int wg   = wid & 3;               // rows wg*16 .. wg*16+15
    const int ltid = tid & 127;
    const int fr = lane & 15, fc = (lane >> 4) << 3;
    const int g  = lane >> 2, t = lane & 3;
    const int vkr = ((lane >> 4) << 3) + (lane & 7);
    const int vnc = ((lane >> 3) & 1) << 3;

    const size_t hb = ((size_t)(b * HEADS + h)) * SEQ * HD;
    const bf16* src_k[4];
    src_k[0] = gkh + hb; src_k[1] = gkl + hb;
    src_k[2] = gvh + hb; src_k[3] = gvl + hb;

    char* gstage = sm + AOFF_STAGE + grp * GRP_STAGE;

    auto issueK = [&](int kb) {
        const size_t koff = (size_t)kb * 64 * HD;
#pragma unroll
        for (int t4 = 0; t4 < 2; t4++) {
#pragma unroll
            for (int j = 0; j < 4; j++) {
                const int ch = ltid + j * 128;     // 0..511
                const int row = ch >> 3, cc = ch & 7;
                unsigned dst = smem_u32(gstage + t4 * ATILE_B + (row * AST + cc * 8) * 2);
                CP_ASYNC16(dst, src_k[t4] + koff + row * HD + cc * 8);
            }
        }
        CP_COMMIT();
    };
    auto issueV = [&](int kb) {
        const size_t koff = (size_t)kb * 64 * HD;
#pragma unroll
        for (int t4 = 2; t4 < 4; t4++) {
#pragma unroll
            for (int j = 0; j < 4; j++) {
                const int ch = ltid + j * 128;
                const int row = ch >> 3, cc = ch & 7;
                unsigned dst = smem_u32(gstage + t4 * ATILE_B + (row * AST + cc * 8) * 2);
                CP_ASYNC16(dst, src_k[t4] + koff + row * HD + cc * 8);
            }
        }
        CP_COMMIT();
    };

    if (grp <= qb) { issueK(grp); issueV(grp); }

    // Q tiles (global loads by all 256 threads)
    {
        const bf16* qh = gqh + hb + (size_t)qb * 64 * HD;
        const bf16* ql = gql + hb + (size_t)qb * 64 * HD;
#pragma unroll
        for (int j = 0; j < 2; j++) {
            const int ch = tid + j * 256;
            const int row = ch >> 3, cc = ch & 7;
            *(uint4*)(sm + (row * AST + cc * 8) * 2) =
                *(const uint4*)(qh + row * HD + cc * 8);
            *(uint4*)(sm + ATILE_B + (row * AST + cc * 8) * 2) =
                *(const uint4*)(ql + row * HD + cc * 8);
        }
    }
    __syncthreads();   // Q visible to both groups

    const unsigned uQh = smem_u32(sm), uQl = uQh + ATILE_B;
    const unsigned uKh = smem_u32(gstage);
    const unsigned uKl = uKh + ATILE_B;
    const unsigned uVh = uKh + 2 * ATILE_B, uVl = uKh + 3 * ATILE_B;

    float o_acc[8][4];
#pragma unroll
    for (int i = 0; i < 8; i++)
#pragma unroll
        for (int j = 0; j < 4; j++) o_acc[i][j] = 0.f;
    float m0r = -1e30f, m1r = -1e30f, l0r = 0.f, l1r = 0.f;

    for (int kb = grp; kb <= qb; kb += 2) {
        CP_WAIT0();          // K(kb), V(kb) resident (no newer commits pending)
        BARG();              // group-wide visibility; prior PV done

        // ---- S = Q K^T over full 64-wide block (3-split) ----
        float sfr[8][4];
#pragma unroll
        for (int i = 0; i < 8; i++)
#pragma unroll
            for (int j = 0; j < 4; j++) sfr[i][j] = 0.f;

#pragma unroll
        for (int ks = 0; ks < 4; ks++) {
            const int kcol = ks * 16 + fc;
            unsigned qa_h[4], qa_l[4];
            const unsigned offa = ((wg * 16 + fr) * AST + kcol) * 2;
            ldsm4(qa_h, uQh + offa);
            ldsm4(qa_l, uQl + offa);
#pragma unroll
            for (int ntp = 0; ntp < 4; ntp++) {
                const unsigned offb = ((ntp * 16 + fr) * AST + kcol) * 2;
                unsigned rh[4], rl[4];
                ldsm4(rh, uKh + offb);
                ldsm4(rl, uKl + offb);
                unsigned bh0[2] = {rh[0], rh[2]}, bh1[2] = {rh[1], rh[3]};
                unsigned bl0[2] = {rl[0], rl[2]}, bl1[2] = {rl[1], rl[3]};
                mma16816(sfr[2*ntp],   qa_h, bh0);
                mma16816(sfr[2*ntp],   qa_h, bl0);
                mma16816(sfr[2*ntp],   qa_l, bh0);
                mma16816(sfr[2*ntp+1], qa_h, bh1);
                mma16816(sfr[2*ntp+1], qa_h, bl1);
                mma16816(sfr[2*ntp+1], qa_l, bh1);
            }
        }

        BARG();                          // K tiles consumed by all group warps
        if (kb + 2 <= qb) issueK(kb + 2);

        // ---- private online softmax (2^x domain) ----
        float pm0 = sfr[0][0], pm1 = sfr[0][2];
#pragma unroll
        for (int nt = 0; nt < 8; nt++) {
            pm0 = fmaxf(pm0, fmaxf(sfr[nt][0], sfr[nt][1]));
            pm1 = fmaxf(pm1, fmaxf(sfr[nt][2], sfr[nt][3]));
        }
        pm0 = fmaxf(pm0, __shfl_xor_sync(0xffffffffu, pm0, 1));
        pm0 = fmaxf(pm0, __shfl_xor_sync(0xffffffffu, pm0, 2));
        pm1 = fmaxf(pm1, __shfl_xor_sync(0xffffffffu, pm1, 1));
        pm1 = fmaxf(pm1, __shfl_xor_sync(0xffffffffu, pm1, 2));

        const float mnew0 = fmaxf(m0r, pm0), mnew1 = fmaxf(m1r, pm1);
        const float corr0 = exp2f(m0r - mnew0), corr1 = exp2f(m1r - mnew1);
        const float pf0 = exp2f(pm0 - mnew0), pf1 = exp2f(pm1 - mnew1);

        float ps0 = 0.f, ps1 = 0.f;
#pragma unroll
        for (int nt = 0; nt < 8; nt++) {
            sfr[nt][0] = exp2f(sfr[nt][0] - pm0);
            sfr[nt][1] = exp2f(sfr[nt][1] - pm0);
            sfr[nt][2] = exp2f(sfr[nt][2] - pm1);
            sfr[nt][3] = exp2f(sfr[nt][3] - pm1);
            ps0 += sfr[nt][0] + sfr[nt][1];
            ps1 += sfr[nt][2] + sfr[nt][3];
        }
        ps0 += __shfl_xor_sync(0xffffffffu, ps0, 1);
        ps0 += __shfl_xor_sync(0xffffffffu, ps0, 2);
        ps1 += __shfl_xor_sync(0xffffffffu, ps1, 1);
        ps1 += __shfl_xor_sync(0xffffffffu, ps1, 2);

        l0r = l0r * corr0 + ps0 * pf0;
        l1r = l1r * corr1 + ps1 * pf1;
        m0r = mnew0; m1r = mnew1;

#pragma unroll
        for (int nt = 0; nt < 8; nt++) {
            sfr[nt][0] *= pf0; sfr[nt][1] *= pf0;
            sfr[nt][2] *= pf1; sfr[nt][3] *= pf1;
        }
#pragma unroll
        for (int n8 = 0; n8 < 8; n8++) {
            o_acc[n8][0] *= corr0; o_acc[n8][1] *= corr0;
            o_acc[n8][2] *= corr1; o_acc[n8][3] *= corr1;
        }

        // ---- O += P V over full k=64 (3-split); P converted per ks2 ----
#pragma unroll
        for (int ks2 = 0; ks2 < 4; ks2++) {
            const int ntA = 2 * ks2, ntB = 2 * ks2 + 1;
            unsigned pa_h[4], pa_l[4];
            {
                const float p00 = sfr[ntA][0], p01 = sfr[ntA][1];
                const float p02 = sfr[ntA][2], p03 = sfr[ntA][3];
                const float p10 = sfr[ntB][0], p11 = sfr[ntB][1];
                const float p12 = sfr[ntB][2], p13 = sfr[ntB][3];
                const bf16 h00 = __float2bfloat16_rn(p00), h01 = __float2bfloat16_rn(p01);
                const bf16 h02 = __float2bfloat16_rn(p02), h03 = __float2bfloat16_rn(p03);
                const bf16 h10 = __float2bfloat16_rn(p10), h11 = __float2bfloat16_rn(p11);
                const bf16 h12 = __float2bfloat16_rn(p12), h13 = __float2bfloat16_rn(p13);
                pa_h[0] = pack_bf16(h00, h01);
                pa_h[1] = pack_bf16(h02, h03);
                pa_h[2] = pack_bf16(h10, h11);
                pa_h[3] = pack_bf16(h12, h13);
                pa_l[0] = pack_bf16(
                    __float2bfloat16_rn(p00 - __bfloat162float(h00)),
                    __float2bfloat16_rn(p01 - __bfloat162float(h01)));
                pa_l[1] = pack_bf16(
                    __float2bfloat16_rn(p02 - __bfloat162float(h02)),
                    __float2bfloat16_rn(p03 - __bfloat162float(h03)));
                pa_l[2] = pack_bf16(
                    __float2bfloat16_rn(p10 - __bfloat162float(h10)),
                    __float2bfloat16_rn(p11 - __bfloat162float(h11)));
                pa_l[3] = pack_bf16(
                    __float2bfloat16_rn(p12 - __bfloat162float(h12)),
                    __float2bfloat16_rn(p13 - __bfloat162float(h13)));
            }
#pragma unroll
            for (int nc = 0; nc < 4; nc++) {
                const unsigned offv =
                    ((ks2 * 16 + vkr) * AST + nc * 16 + vnc) * 2;
                unsigned rh[4], rl[4];
                ldsm4t(rh, uVh + offv);
                ldsm4t(rl, uVl + offv);
                unsigned bh0[2] = {rh[0], rh[2]}, bh1[2] = {rh[1], rh[3]};
                unsigned bl0[2] = {rl[0], rl[2]}, bl1[2] = {rl[1], rl[3]};
                mma16816(o_acc[nc*2],   pa_h, bh0);
                mma16816(o_acc[nc*2],   pa_h, bl0);
                mma16816(o_acc[nc*2],   pa_l, bh0);
                mma16816(o_acc[nc*2+1], pa_h, bh1);
                mma16816(o_acc[nc*2+1], pa_h, bl1);
                mma16816(o_acc[nc*2+1], pa_l, bh1);
            }
        }

        BARG();                          // V tiles consumed
        if (kb + 2 <= qb) issueV(kb + 2);
    }
    __syncthreads();   // both groups done before staging reuse

    // Final group-merge + output. Group 1 publishes (O, m, l); group 0 merges.
    float* red = (float*)(sm + AOFF_STAGE);     // [64][66]
    float* mB  = (float*)(sm + AOFF_XM);        // [64]
    float* lB  = mB + 64;                       // [64]
    if (grp == 1) {
#pragma unroll
        for (int n8 = 0; n8 < 8; n8++) {
            const int col = n8 * 8 + 2 * t;
            red[(wg * 16 + g)     * 66 + col]     = o_acc[n8][0];
            red[(wg * 16 + g)     * 66 + col + 1] = o_acc[n8][1];
            red[(wg * 16 + g + 8) * 66 + col]     = o_acc[n8][2];
            red[(wg * 16 + g + 8) * 66 + col + 1] = o_acc[n8][3];
        }
        if (t == 0) {
            mB[wg * 16 + g]     = m0r;  lB[wg * 16 + g]     = l0r;
            mB[wg * 16 + g + 8] = m1r;  lB[wg * 16 + g + 8] = l1r;
        }
    }
    __syncthreads();
    if (grp == 0) {
        const int r0 = wg * 16 + g;
        const float mb0 = mB[r0],     lb0 = lB[r0];
        const float mb1 = mB[r0 + 8], lb1 = lB[r0 + 8];
        const float mf0 = fmaxf(m0r, mb0), mf1 = fmaxf(m1r, mb1);
        const float sA0 = exp2f(m0r - mf0), sB0 = exp2f(mb0 - mf0);
        const float sA1 = exp2f(m1r - mf1), sB1 = exp2f(mb1 - mf1);
        const float inv0 = 1.f / (l0r * sA0 + lb0 * sB0);
        const float inv1 = 1.f / (l1r * sA1 + lb1 * sB1);
        const size_t obase = ((size_t)(b * SEQ + qb * 64)) * HIDN + h * HD;
#pragma unroll
        for (int n8 = 0; n8 < 8; n8++) {
            const int col = n8 * 8 + 2 * t;
            const float v0 = (o_acc[n8][0] * sA0 + red[r0*66 + col]     * sB0) * inv0;
            const float v1 = (o_acc[n8][1] * sA0 + red[r0*66 + col + 1] * sB0) * inv0;
            const float v2 = (o_acc[n8][2] * sA1 + red[(r0+8)*66 + col]     * sB1) * inv1;
            const float v3 = (o_acc[n8][3] * sA1 + red[(r0+8)*66 + col + 1] * sB1) * inv1;
            const bf16 h0 = __float2bfloat16_rn(v0), h1 = __float2bfloat16_rn(v1);
            const bf16 h2 = __float2bfloat16_rn(v2), h3 = __float2bfloat16_rn(v3);
            const size_t i0 = obase + (size_t)r0 * HIDN + col;
            const size_t i1 = obase + (size_t)(r0 + 8) * HIDN + col;
            *(unsigned*)(goh + i0) = pack_bf16(h0, h1);
            *(unsigned*)(gol + i0) = pack_bf16(
                __float2bfloat16_rn(v0 - __bfloat162float(h0)),
                __float2bfloat16_rn(v1 - __bfloat162float(h1)));
            *(unsigned*)(goh + i1) = pack_bf16(h2, h3);
            *(unsigned*)(gol + i1) = pack_bf16(
                __float2bfloat16_rn(v2 - __bfloat162float(h2)),
                __float2bfloat16_rn(v3 - __bfloat162float(h3)));
        }
    }
}

// ---------------------------------------------------------------------------
extern "C" void kernel_launch(void* const* d_in, const int* in_sizes, int n_in,
                              void* d_out, int out_size)
{
    const float* x  = (const float*)d_in[0];
    const float* Wq = (const float*)d_in[1];
    const float* bq = (const float*)d_in[2];
    const float* Wk = (const float*)d_in[3];
    const float* bk = (const float*)d_in[4];
    const float* Wv = (const float*)d_in[5];
    const float* bv = (const float*)d_in[6];
    const float* Wo = (const float*)d_in[7];
    const float* bo = (const float*)d_in[8];
    float* out = (float*)d_out;

    bf16 *xh, *xl, *w8, *qh, *ql, *kh, *kl, *vh, *vl, *ah, *al;
    unsigned* ctr;
    cudaGetSymbolAddress((void**)&xh, g_xh);
    cudaGetSymbolAddress((void**)&xl, g_xl);
    cudaGetSymbolAddress((void**)&w8, g_w8);
    cudaGetSymbolAddress((void**)&qh, g_qh);
    cudaGetSymbolAddress((void**)&ql, g_ql);
    cudaGetSymbolAddress((void**)&kh, g_kh);
    cudaGetSymbolAddress((void**)&kl, g_kl);
    cudaGetSymbolAddress((void**)&vh, g_vh);
    cudaGetSymbolAddress((void**)&vl, g_vl);
    cudaGetSymbolAddress((void**)&ah, g_ah);
    cudaGetSymbolAddress((void**)&al, g_al);
    cudaGetSymbolAddress((void**)&ctr, g_ctr);

    cudaFuncSetAttribute(gemm_pers,
                         cudaFuncAttributeMaxDynamicSharedMemorySize, GSM_BYTES);
    cudaFuncSetAttribute(attn_mma2,
                         cudaFuncAttributeMaxDynamicSharedMemorySize, ATTN_SMEM);

    const int W2 = HIDN * HIDN;

    // One fused launch: x + Wq/Wk/Wv/Wo splits + counter reset
    split_all<<<XBLK + 4 * WBLK, 256>>>(x, Wq, Wk, Wv, Wo, xh, xl, w8);

    // Q scale folds softmax's log2(e) so attention can use pure exp2
    Job jq = { w8 + 0*W2, w8 + 1*W2, bq, qh, ql, nullptr,
               0.125f * 1.44269504088896f };
    Job jk = { w8 + 2*W2, w8 + 3*W2, bk, kh, kl, nullptr, 1.0f };
    Job jv = { w8 + 4*W2, w8 + 5*W2, bv, vh, vl, nullptr, 1.0f };
    Job jo = { w8 + 6*W2, w8 + 7*W2, bo, nullptr, nullptr, out, 1.0f };

    // Fused QKV: 768 tiles, dynamic stealing over 296 persistent CTAs
    gemm_pers<<<296, 256, GSM_BYTES>>>(ctr + 0, 768, xh, xl, jq, jk, jv);

    attn_mma2<<<dim3(NQB, HEADS, BSZ), 256, ATTN_SMEM>>>(qh, ql, kh, kl,
                                                         vh, vl, ah, al);

    // O projection: 256 tiles
    gemm_pers<<<296, 256, GSM_BYTES>>>(ctr + 1, 256, ah, al, jo, jo, jo);
}